// round 1
// baseline (speedup 1.0000x reference)
#include <cuda_runtime.h>
#include <math.h>

// ---------------------------------------------------------------------------
// MemoryGatedAttention  (B=4, T=S=2048, D=1024, H=16, DH=64, M=64)
//   Q = q@Wq+bq; K = k@Wk+bk; V = v@Wv+bv          (sgemm_bias)
//   gate = mean(sigmoid(concat(mean_t q, mean_m mem) @ Wg + bg))
//   attn = softmax(QK^T * gate / sqrt(DH)); O = attn@V  (flash_kernel)
//   out = O@Wo + bo                                  (sgemm_bias -> d_out)
// Round 1: fp32 SIMT baseline (correctness + roofline probe). Tensor-core
// (tf32 tcgen05) port planned for later rounds.
// ---------------------------------------------------------------------------

namespace cfg {
constexpr int B  = 4;
constexpr int T  = 2048;
constexpr int S  = 2048;
constexpr int D  = 1024;
constexpr int H  = 16;
constexpr int DH = 64;
constexpr int M  = 64;
constexpr int BT = B * T;              // 8192 rows for the projection GEMMs
constexpr int LD = 68;                 // smem row stride (floats): 16B-aligned, bank-skewed
constexpr int FLASH_SMEM = 4 * 64 * LD * (int)sizeof(float);   // 69632 bytes
}

// ----------------------------- scratch (static; no allocs allowed) ----------
__device__ float g_Q[cfg::B * cfg::T * cfg::D];
__device__ float g_K[cfg::B * cfg::S * cfg::D];
__device__ float g_V[cfg::B * cfg::S * cfg::D];
__device__ float g_O[cfg::B * cfg::T * cfg::D];
__device__ float g_memin[cfg::B * 2 * cfg::D];     // [B, 2D]
__device__ float g_gatevals[cfg::B * cfg::D];      // [B, D] sigmoid values
__device__ float g_scale_val;                      // gate / sqrt(DH)

// ----------------------------- means ---------------------------------------
__global__ void __launch_bounds__(256)
mean_kernel(const float* __restrict__ query, const float* __restrict__ memory)
{
    using namespace cfg;
    const int b = blockIdx.y;
    const int d = blockIdx.x * blockDim.x + threadIdx.x;     // 0..D-1

    const float* qp = query + (size_t)b * T * D + d;
    float s0 = 0.f, s1 = 0.f, s2 = 0.f, s3 = 0.f;
    for (int t = 0; t < T; t += 4) {
        s0 += qp[(size_t)(t + 0) * D];
        s1 += qp[(size_t)(t + 1) * D];
        s2 += qp[(size_t)(t + 2) * D];
        s3 += qp[(size_t)(t + 3) * D];
    }
    g_memin[b * 2 * D + d] = ((s0 + s1) + (s2 + s3)) * (1.0f / T);

    const float* mp = memory + (size_t)b * M * D + d;
    float u0 = 0.f, u1 = 0.f;
    for (int m = 0; m < M; m += 2) {
        u0 += mp[(size_t)(m + 0) * D];
        u1 += mp[(size_t)(m + 1) * D];
    }
    g_memin[b * 2 * D + D + d] = (u0 + u1) * (1.0f / M);
}

// ----------------------------- gate ----------------------------------------
__global__ void __launch_bounds__(256)
gate_vals_kernel(const float* __restrict__ Wg, const float* __restrict__ bg)
{
    using namespace cfg;
    const int b = blockIdx.y;
    const int j = blockIdx.x * blockDim.x + threadIdx.x;     // 0..D-1
    const float* mi = g_memin + b * 2 * D;

    float a0 = 0.f, a1 = 0.f, a2 = 0.f, a3 = 0.f;
    for (int i = 0; i < 2 * D; i += 4) {
        a0 += mi[i + 0] * Wg[(size_t)(i + 0) * D + j];
        a1 += mi[i + 1] * Wg[(size_t)(i + 1) * D + j];
        a2 += mi[i + 2] * Wg[(size_t)(i + 2) * D + j];
        a3 += mi[i + 3] * Wg[(size_t)(i + 3) * D + j];
    }
    float acc = bg[j] + ((a0 + a1) + (a2 + a3));
    g_gatevals[b * D + j] = 1.0f / (1.0f + expf(-acc));
}

// deterministic single-block reduction -> scalar (no float atomics)
__global__ void gate_reduce_kernel()
{
    using namespace cfg;
    __shared__ float red[1024];
    const int t = threadIdx.x;
    red[t] = g_gatevals[t] + g_gatevals[t + 1024] +
             g_gatevals[t + 2048] + g_gatevals[t + 3072];
    __syncthreads();
    for (int s = 512; s > 0; s >>= 1) {
        if (t < s) red[t] += red[t + s];
        __syncthreads();
    }
    if (t == 0) {
        // (sum / (B*D)) / sqrt(DH)
        g_scale_val = red[0] * (1.0f / (B * D)) * 0.125f;
    }
}

// ----------------------------- SGEMM: C = A*W + bias ------------------------
// A: [Mrows,Kdim] row-major, W: [Kdim,N] row-major, C: [Mrows,N].
// 128x128 block, BK=8, 256 threads, 8x8 per thread (split 4+64 fragments).
__global__ void __launch_bounds__(256)
sgemm_bias_kernel(const float* __restrict__ A, const float* __restrict__ W,
                  const float* __restrict__ bias, float* __restrict__ C,
                  int Mrows, int N, int Kdim)
{
    __shared__ float As[8][128];   // As[k][m]  (A tile transposed)
    __shared__ float Bs[8][128];   // Bs[k][n]

    const int tid = threadIdx.x;
    const int m0 = blockIdx.y * 128;
    const int n0 = blockIdx.x * 128;
    const int tr = tid >> 4;                 // 0..15
    const int tc = tid & 15;                 // 0..15
    const int aRow = tid >> 1;               // 0..127
    const int aCol = (tid & 1) * 4;          // 0 or 4
    const int bRow = tid >> 5;               // 0..7
    const int bCol = (tid & 31) * 4;         // 0..124

    const float* Ap = A + (size_t)(m0 + aRow) * Kdim + aCol;
    const float* Bp = W + (size_t)bRow * N + n0 + bCol;

    float acc[8][8];
#pragma unroll
    for (int i = 0; i < 8; i++)
#pragma unroll
        for (int j = 0; j < 8; j++) acc[i][j] = 0.f;

    for (int k0 = 0; k0 < Kdim; k0 += 8) {
        float4 av = *(const float4*)(Ap + k0);
        float4 bv = *(const float4*)(Bp + (size_t)k0 * N);
        As[aCol + 0][aRow] = av.x;
        As[aCol + 1][aRow] = av.y;
        As[aCol + 2][aRow] = av.z;
        As[aCol + 3][aRow] = av.w;
        *(float4*)&Bs[bRow][bCol] = bv;
        __syncthreads();

#pragma unroll
        for (int kk = 0; kk < 8; kk++) {
            float4 a0 = *(const float4*)&As[kk][tr * 4];
            float4 a1 = *(const float4*)&As[kk][64 + tr * 4];
            float4 b0 = *(const float4*)&Bs[kk][tc * 4];
            float4 b1 = *(const float4*)&Bs[kk][64 + tc * 4];
            float aa[8] = {a0.x, a0.y, a0.z, a0.w, a1.x, a1.y, a1.z, a1.w};
            float bb[8] = {b0.x, b0.y, b0.z, b0.w, b1.x, b1.y, b1.z, b1.w};
#pragma unroll
            for (int i = 0; i < 8; i++)
#pragma unroll
                for (int j = 0; j < 8; j++)
                    acc[i][j] += aa[i] * bb[j];
        }
        __syncthreads();
    }

    float4 blo = *(const float4*)(bias + n0 + tc * 4);
    float4 bhi = *(const float4*)(bias + n0 + 64 + tc * 4);
    float bl[8] = {blo.x, blo.y, blo.z, blo.w, bhi.x, bhi.y, bhi.z, bhi.w};

#pragma unroll
    for (int i = 0; i < 8; i++) {
        int row = m0 + ((i < 4) ? (tr * 4 + i) : (64 + tr * 4 + (i - 4)));
        float* cp = C + (size_t)row * N + n0;
        *(float4*)(cp + tc * 4) =
            make_float4(acc[i][0] + bl[0], acc[i][1] + bl[1],
                        acc[i][2] + bl[2], acc[i][3] + bl[3]);
        *(float4*)(cp + 64 + tc * 4) =
            make_float4(acc[i][4] + bl[4], acc[i][5] + bl[5],
                        acc[i][6] + bl[6], acc[i][7] + bl[7]);
    }
}

// ----------------------------- flash attention ------------------------------
// grid (T/64, H, B), 256 threads. 64x64 score tiles, 4x4 per thread.
// Smem: Qst[d][r], Kst[d][c], Vs[s][c], Pst[s][r], all rows stride LD=68.
__global__ void __launch_bounds__(256)
flash_kernel(const float* __restrict__ Q, const float* __restrict__ K,
             const float* __restrict__ V, float* __restrict__ O)
{
    using namespace cfg;
    extern __shared__ float sm[];
    float* Qst = sm;                  // [64][LD]
    float* Kst = sm + 64 * LD;        // [64][LD]
    float* Vs  = sm + 2 * 64 * LD;    // [64][LD]
    float* Pst = sm + 3 * 64 * LD;    // [64][LD]

    const int b  = blockIdx.z;
    const int h  = blockIdx.y;
    const int q0 = blockIdx.x * 64;
    const int tid = threadIdx.x;
    const float gscale = g_scale_val;     // gate / sqrt(DH)

    // load Q tile transposed: Qst[d][r]
    {
        const int rr = tid >> 2;
        const int d0 = (tid & 3) * 16;
        const float* src = Q + (size_t)(b * T + q0 + rr) * D + h * DH + d0;
#pragma unroll
        for (int j = 0; j < 16; j += 4) {
            float4 v = *(const float4*)(src + j);
            Qst[(d0 + j + 0) * LD + rr] = v.x;
            Qst[(d0 + j + 1) * LD + rr] = v.y;
            Qst[(d0 + j + 2) * LD + rr] = v.z;
            Qst[(d0 + j + 3) * LD + rr] = v.w;
        }
    }

    const int r4 = (tid >> 4) << 2;   // query-row group (4 rows)
    const int c4 = (tid & 15) << 2;   // key-col  group (4 cols)

    float m_i[4], l_i[4], acc[4][4];
#pragma unroll
    for (int i = 0; i < 4; i++) {
        m_i[i] = -INFINITY;
        l_i[i] = 0.f;
#pragma unroll
        for (int j = 0; j < 4; j++) acc[i][j] = 0.f;
    }

    for (int s0 = 0; s0 < S; s0 += 64) {
        // load K tile transposed (Kst[d][c]) + V tile direct (Vs[s][c])
        {
            const int cc = tid >> 2;
            const int d0 = (tid & 3) * 16;
            const float* ks = K + (size_t)(b * S + s0 + cc) * D + h * DH + d0;
            const float* vs = V + (size_t)(b * S + s0 + cc) * D + h * DH + d0;
#pragma unroll
            for (int j = 0; j < 16; j += 4) {
                float4 kv = *(const float4*)(ks + j);
                Kst[(d0 + j + 0) * LD + cc] = kv.x;
                Kst[(d0 + j + 1) * LD + cc] = kv.y;
                Kst[(d0 + j + 2) * LD + cc] = kv.z;
                Kst[(d0 + j + 3) * LD + cc] = kv.w;
                float4 vv = *(const float4*)(vs + j);
                *(float4*)(Vs + cc * LD + d0 + j) = vv;
            }
        }
        __syncthreads();

        // ---- scores: sc[i][j] = sum_d Q[r4+i][d] * K[c4+j][d]
        float sc[4][4];
#pragma unroll
        for (int i = 0; i < 4; i++)
#pragma unroll
            for (int j = 0; j < 4; j++) sc[i][j] = 0.f;

#pragma unroll 8
        for (int d = 0; d < DH; d++) {
            float4 q4 = *(const float4*)(Qst + d * LD + r4);
            float4 k4 = *(const float4*)(Kst + d * LD + c4);
            float qa[4] = {q4.x, q4.y, q4.z, q4.w};
            float ka[4] = {k4.x, k4.y, k4.z, k4.w};
#pragma unroll
            for (int i = 0; i < 4; i++)
#pragma unroll
                for (int j = 0; j < 4; j++)
                    sc[i][j] += qa[i] * ka[j];
        }

        // scale + row max (16-thread group = same half-warp -> shfl_xor)
        float rmax[4];
#pragma unroll
        for (int i = 0; i < 4; i++) {
            sc[i][0] *= gscale; sc[i][1] *= gscale;
            sc[i][2] *= gscale; sc[i][3] *= gscale;
            rmax[i] = fmaxf(fmaxf(sc[i][0], sc[i][1]), fmaxf(sc[i][2], sc[i][3]));
        }
#pragma unroll
        for (int off = 1; off < 16; off <<= 1)
#pragma unroll
            for (int i = 0; i < 4; i++)
                rmax[i] = fmaxf(rmax[i], __shfl_xor_sync(0xffffffffu, rmax[i], off));

        // online softmax update
        float p[4][4], psum[4];
#pragma unroll
        for (int i = 0; i < 4; i++) {
            float nm = fmaxf(m_i[i], rmax[i]);
            float corr = __expf(m_i[i] - nm);
            m_i[i] = nm;
            float ps = 0.f;
#pragma unroll
            for (int j = 0; j < 4; j++) {
                p[i][j] = __expf(sc[i][j] - nm);
                ps += p[i][j];
            }
            psum[i] = ps;
            l_i[i] *= corr;
#pragma unroll
            for (int j = 0; j < 4; j++) acc[i][j] *= corr;
        }
#pragma unroll
        for (int off = 1; off < 16; off <<= 1)
#pragma unroll
            for (int i = 0; i < 4; i++)
                psum[i] += __shfl_xor_sync(0xffffffffu, psum[i], off);
#pragma unroll
        for (int i = 0; i < 4; i++) l_i[i] += psum[i];

        // store probabilities transposed: Pst[s][r]
#pragma unroll
        for (int i = 0; i < 4; i++)
#pragma unroll
            for (int j = 0; j < 4; j++)
                Pst[(c4 + j) * LD + r4 + i] = p[i][j];
        __syncwarp();   // Pst producer/consumer pairs share a warp

        // ---- PV: acc[i][j] += sum_s P[r4+i][s] * V[s][c4+j]
#pragma unroll 8
        for (int s = 0; s < 64; s++) {
            float4 p4 = *(const float4*)(Pst + s * LD + r4);
            float4 v4 = *(const float4*)(Vs + s * LD + c4);
            float pa[4] = {p4.x, p4.y, p4.z, p4.w};
            float va[4] = {v4.x, v4.y, v4.z, v4.w};
#pragma unroll
            for (int i = 0; i < 4; i++)
#pragma unroll
                for (int j = 0; j < 4; j++)
                    acc[i][j] += pa[i] * va[j];
        }
        __syncthreads();   // all reads of Kst/Vs/Pst done before next tile
    }

    // epilogue: normalize and store
#pragma unroll
    for (int i = 0; i < 4; i++) {
        float inv = 1.0f / l_i[i];
        float4 o = make_float4(acc[i][0] * inv, acc[i][1] * inv,
                               acc[i][2] * inv, acc[i][3] * inv);
        *(float4*)(O + (size_t)(b * T + q0 + r4 + i) * D + h * DH + c4) = o;
    }
}

// ----------------------------- launch ---------------------------------------
extern "C" void kernel_launch(void* const* d_in, const int* in_sizes, int n_in,
                              void* d_out, int out_size)
{
    using namespace cfg;
    (void)in_sizes; (void)n_in; (void)out_size;

    const float* query  = (const float*)d_in[0];
    const float* key    = (const float*)d_in[1];
    const float* value  = (const float*)d_in[2];
    const float* memory = (const float*)d_in[3];
    const float* Wq = (const float*)d_in[4];
    const float* bq = (const float*)d_in[5];
    const float* Wk = (const float*)d_in[6];
    const float* bk = (const float*)d_in[7];
    const float* Wv = (const float*)d_in[8];
    const float* bv = (const float*)d_in[9];
    const float* Wo = (const float*)d_in[10];
    const float* bo = (const float*)d_in[11];
    const float* Wg = (const float*)d_in[12];
    const float* bg = (const float*)d_in[13];
    float* out = (float*)d_out;

    void *pQ, *pK, *pV, *pO;
    cudaGetSymbolAddress(&pQ, g_Q);
    cudaGetSymbolAddress(&pK, g_K);
    cudaGetSymbolAddress(&pV, g_V);
    cudaGetSymbolAddress(&pO, g_O);

    // opt-in for 69.6KB dynamic smem (non-stream call; capture-safe, idempotent)
    cudaFuncSetAttribute(flash_kernel,
                         cudaFuncAttributeMaxDynamicSharedMemorySize, FLASH_SMEM);

    // gate path
    mean_kernel<<<dim3(D / 256, B), 256>>>(query, memory);
    gate_vals_kernel<<<dim3(D / 256, B), 256>>>(Wg, bg);
    gate_reduce_kernel<<<1, 1024>>>();

    // projections
    dim3 gg(D / 128, BT / 128);
    sgemm_bias_kernel<<<gg, 256>>>(query, Wq, bq, (float*)pQ, BT, D, D);
    sgemm_bias_kernel<<<gg, 256>>>(key,   Wk, bk, (float*)pK, BT, D, D);
    sgemm_bias_kernel<<<gg, 256>>>(value, Wv, bv, (float*)pV, BT, D, D);

    // attention
    flash_kernel<<<dim3(T / 64, H, B), 256, FLASH_SMEM>>>(
        (const float*)pQ, (const float*)pK, (const float*)pV, (float*)pO);

    // output projection -> d_out
    sgemm_bias_kernel<<<gg, 256>>>((const float*)pO, Wo, bo, out, BT, D, D);
}

// round 2
// speedup vs baseline: 1.3173x; 1.3173x over previous
#include <cuda_runtime.h>
#include <mma.h>
#include <math.h>

using namespace nvcuda;

// ---------------------------------------------------------------------------
// MemoryGatedAttention  (B=4, T=S=2048, D=1024, H=16, DH=64, M=64)
// Round 2: tf32 wmma tensor-core path for all GEMM-shaped work.
// ---------------------------------------------------------------------------

namespace cfg {
constexpr int B  = 4;
constexpr int T  = 2048;
constexpr int S  = 2048;
constexpr int D  = 1024;
constexpr int H  = 16;
constexpr int DH = 64;
constexpr int M  = 64;
constexpr int BT = B * T;
// flash smem: 3 tiles [64][72] + m/l/corr[64]*3 + idx[256]
constexpr int FL_SMEM_FLOATS = 3 * 64 * 72 + 3 * 64 + 256;   // 14272
constexpr int FL_SMEM = FL_SMEM_FLOATS * (int)sizeof(float); // 57088 B
}

// ----------------------------- scratch (static; no allocs allowed) ----------
__device__ float g_Q[cfg::B * cfg::T * cfg::D];
__device__ float g_K[cfg::B * cfg::S * cfg::D];
__device__ float g_V[cfg::B * cfg::S * cfg::D];
__device__ float g_O[cfg::B * cfg::T * cfg::D];
__device__ float g_memin[cfg::B * 2 * cfg::D];
__device__ float g_gatevals[cfg::B * cfg::D];
__device__ float g_scale_val;                      // gate / sqrt(DH)

// ----------------------------- fragment types -------------------------------
using FragA  = wmma::fragment<wmma::matrix_a, 16, 16, 8, wmma::precision::tf32, wmma::row_major>;
using FragBr = wmma::fragment<wmma::matrix_b, 16, 16, 8, wmma::precision::tf32, wmma::row_major>;
using FragBc = wmma::fragment<wmma::matrix_b, 16, 16, 8, wmma::precision::tf32, wmma::col_major>;
using FragC  = wmma::fragment<wmma::accumulator, 16, 16, 8, float>;

template <typename F>
__device__ __forceinline__ void to_tf32(F& f) {
#pragma unroll
    for (int e = 0; e < f.num_elements; e++) f.x[e] = wmma::__float_to_tf32(f.x[e]);
}

// ----------------------------- means ---------------------------------------
__global__ void __launch_bounds__(256)
mean_kernel(const float* __restrict__ query, const float* __restrict__ memory)
{
    using namespace cfg;
    const int b = blockIdx.y;
    const int d = blockIdx.x * blockDim.x + threadIdx.x;

    const float* qp = query + (size_t)b * T * D + d;
    float s0 = 0.f, s1 = 0.f, s2 = 0.f, s3 = 0.f;
    for (int t = 0; t < T; t += 4) {
        s0 += qp[(size_t)(t + 0) * D];
        s1 += qp[(size_t)(t + 1) * D];
        s2 += qp[(size_t)(t + 2) * D];
        s3 += qp[(size_t)(t + 3) * D];
    }
    g_memin[b * 2 * D + d] = ((s0 + s1) + (s2 + s3)) * (1.0f / T);

    const float* mp = memory + (size_t)b * M * D + d;
    float u0 = 0.f, u1 = 0.f;
    for (int m = 0; m < M; m += 2) {
        u0 += mp[(size_t)(m + 0) * D];
        u1 += mp[(size_t)(m + 1) * D];
    }
    g_memin[b * 2 * D + D + d] = (u0 + u1) * (1.0f / M);
}

// ----------------------------- gate ----------------------------------------
__global__ void __launch_bounds__(256)
gate_vals_kernel(const float* __restrict__ Wg, const float* __restrict__ bg)
{
    using namespace cfg;
    const int b = blockIdx.y;
    const int j = blockIdx.x * blockDim.x + threadIdx.x;
    const float* mi = g_memin + b * 2 * D;

    float a0 = 0.f, a1 = 0.f, a2 = 0.f, a3 = 0.f;
    for (int i = 0; i < 2 * D; i += 4) {
        a0 += mi[i + 0] * Wg[(size_t)(i + 0) * D + j];
        a1 += mi[i + 1] * Wg[(size_t)(i + 1) * D + j];
        a2 += mi[i + 2] * Wg[(size_t)(i + 2) * D + j];
        a3 += mi[i + 3] * Wg[(size_t)(i + 3) * D + j];
    }
    float acc = bg[j] + ((a0 + a1) + (a2 + a3));
    g_gatevals[b * D + j] = 1.0f / (1.0f + expf(-acc));
}

__global__ void gate_reduce_kernel()
{
    using namespace cfg;
    __shared__ float red[1024];
    const int t = threadIdx.x;
    red[t] = g_gatevals[t] + g_gatevals[t + 1024] +
             g_gatevals[t + 2048] + g_gatevals[t + 3072];
    __syncthreads();
    for (int s = 512; s > 0; s >>= 1) {
        if (t < s) red[t] += red[t + s];
        __syncthreads();
    }
    if (t == 0) g_scale_val = red[0] * (1.0f / (B * D)) * 0.125f;
}

// ----------------------------- tf32 GEMM: C = A*W + bias --------------------
// A:[Mrows,K] row-major, W:[K,N] row-major. 128x128x16 tile, 8 warps (2x4),
// warp tile 64x32 = 4x2 wmma fragments.
__global__ void __launch_bounds__(256)
gemm_tf32_kernel(const float* __restrict__ A, const float* __restrict__ W,
                 const float* __restrict__ bias, float* __restrict__ C,
                 int Mrows, int N, int Kdim)
{
    __shared__ float As[128][20];     // [m][k], pad 4
    __shared__ float Bs[16][132];     // [k][n], pad 4
    __shared__ float idxm[256];

    const int tid = threadIdx.x;
    const int warpId = tid >> 5;
    const int wr = warpId >> 2;       // 0..1 -> rows 64*wr
    const int wc = warpId & 3;        // 0..3 -> cols 32*wc
    const int m0 = blockIdx.y * 128;
    const int n0 = blockIdx.x * 128;

    idxm[tid] = (float)(tid & 15);    // column index within 16x16 tile
    __syncthreads();
    FragC colidx;
    wmma::load_matrix_sync(colidx, idxm, 16, wmma::mem_row_major);

    FragC acc[4][2];
#pragma unroll
    for (int i = 0; i < 4; i++)
#pragma unroll
        for (int j = 0; j < 2; j++) wmma::fill_fragment(acc[i][j], 0.f);

    for (int k0 = 0; k0 < Kdim; k0 += 16) {
        // A tile: 128x16 = 512 float4, 2 per thread
#pragma unroll
        for (int t = 0; t < 2; t++) {
            int idx = tid + t * 256;
            int row = idx >> 2, c4 = idx & 3;
            *(float4*)&As[row][c4 * 4] =
                *(const float4*)(A + (size_t)(m0 + row) * Kdim + k0 + c4 * 4);
        }
        // B tile: 16x128 = 512 float4
#pragma unroll
        for (int t = 0; t < 2; t++) {
            int idx = tid + t * 256;
            int row = idx >> 5, c4 = idx & 31;
            *(float4*)&Bs[row][c4 * 4] =
                *(const float4*)(W + (size_t)(k0 + row) * N + n0 + c4 * 4);
        }
        __syncthreads();

#pragma unroll
        for (int kk = 0; kk < 2; kk++) {
            FragA af[4];
#pragma unroll
            for (int i = 0; i < 4; i++) {
                wmma::load_matrix_sync(af[i], &As[64 * wr + 16 * i][8 * kk], 20);
                to_tf32(af[i]);
            }
            FragBr bf[2];
#pragma unroll
            for (int j = 0; j < 2; j++) {
                wmma::load_matrix_sync(bf[j], &Bs[8 * kk][32 * wc + 16 * j], 132);
                to_tf32(bf[j]);
            }
#pragma unroll
            for (int i = 0; i < 4; i++)
#pragma unroll
                for (int j = 0; j < 2; j++)
                    wmma::mma_sync(acc[i][j], af[i], bf[j], acc[i][j]);
        }
        __syncthreads();
    }

    // epilogue: bias via column-index fragment, store direct to global
#pragma unroll
    for (int i = 0; i < 4; i++)
#pragma unroll
        for (int j = 0; j < 2; j++) {
            const int nbase = n0 + 32 * wc + 16 * j;
#pragma unroll
            for (int e = 0; e < 8; e++)
                acc[i][j].x[e] += __ldg(&bias[nbase + (int)colidx.x[e]]);
            wmma::store_matrix_sync(
                C + (size_t)(m0 + 64 * wr + 16 * i) * N + nbase,
                acc[i][j], N, wmma::mem_row_major);
        }
}

// ----------------------------- tf32 flash attention -------------------------
// grid (T/64, H, B), 256 threads (8 warps, 4x2). 64x64 tiles.
__global__ void __launch_bounds__(256)
flash_tf32_kernel(const float* __restrict__ Q, const float* __restrict__ K,
                  const float* __restrict__ V, float* __restrict__ O)
{
    using namespace cfg;
    extern __shared__ float sm[];
    float* Ks     = sm;            // [64][72]  Ks[c][d]
    float* Vs     = sm + 4608;     // [64][72]  Vs[s][d]
    float* Ss     = sm + 9216;     // [64][72]  S then P in-place
    float* m_s    = sm + 13824;    // [64]
    float* l_s    = m_s + 64;
    float* corr_s = l_s + 64;
    float* idxm   = corr_s + 64;   // [256]

    const int b = blockIdx.z, h = blockIdx.y, q0 = blockIdx.x * 64;
    const int tid = threadIdx.x;
    const int warpId = tid >> 5;
    const int wr = warpId >> 1;    // 0..3 -> rows 16*wr
    const int wc = warpId & 1;     // 0..1 -> cols 32*wc
    const float gscale = g_scale_val;

    idxm[tid] = (float)(tid >> 4);           // row index within 16x16 tile
    if (tid < 64) { m_s[tid] = -INFINITY; l_s[tid] = 0.f; }

    // stage Q tile into Ss
    {
        const int r = tid >> 2;
        const float* src = Q + (size_t)(b * T + q0 + r) * D + h * DH;
#pragma unroll
        for (int j = 0; j < 4; j++) {
            int f = (tid & 3) + j * 4;
            *(float4*)&Ss[r * 72 + f * 4] = *(const float4*)(src + f * 4);
        }
    }
    __syncthreads();

    FragC rowidx;
    wmma::load_matrix_sync(rowidx, idxm, 16, wmma::mem_row_major);

    FragA qf[8];
#pragma unroll
    for (int k = 0; k < 8; k++) {
        wmma::load_matrix_sync(qf[k], &Ss[(16 * wr) * 72 + k * 8], 72);
        to_tf32(qf[k]);
    }
    FragC of[2];
    wmma::fill_fragment(of[0], 0.f);
    wmma::fill_fragment(of[1], 0.f);
    __syncthreads();   // Q staging reads done before Ss reused for S

    for (int s0 = 0; s0 < S; s0 += 64) {
        // load K,V tiles (row = key index, 64 floats of head dim)
        {
            const int r = tid >> 2;
            const float* ksrc = K + (size_t)(b * S + s0 + r) * D + h * DH;
            const float* vsrc = V + (size_t)(b * S + s0 + r) * D + h * DH;
#pragma unroll
            for (int j = 0; j < 4; j++) {
                int f = (tid & 3) + j * 4;
                *(float4*)&Ks[r * 72 + f * 4] = *(const float4*)(ksrc + f * 4);
                *(float4*)&Vs[r * 72 + f * 4] = *(const float4*)(vsrc + f * 4);
            }
        }
        __syncthreads();

        // ---- S = Q K^T (K tile is [c][d] -> matrix_b col_major)
        FragC sf[2];
        wmma::fill_fragment(sf[0], 0.f);
        wmma::fill_fragment(sf[1], 0.f);
#pragma unroll
        for (int k = 0; k < 8; k++) {
#pragma unroll
            for (int j = 0; j < 2; j++) {
                FragBc bf;
                wmma::load_matrix_sync(bf, &Ks[(32 * wc + 16 * j) * 72 + k * 8], 72);
                to_tf32(bf);
                wmma::mma_sync(sf[j], qf[k], bf, sf[j]);
            }
        }
        wmma::store_matrix_sync(&Ss[(16 * wr) * 72 + 32 * wc], sf[0], 72, wmma::mem_row_major);
        wmma::store_matrix_sync(&Ss[(16 * wr) * 72 + 32 * wc + 16], sf[1], 72, wmma::mem_row_major);
        __syncthreads();

        // ---- online softmax (4 threads per row, 16 cols each; quad shfl)
        {
            const int r = tid >> 2, qd = tid & 3;
            float* row = &Ss[r * 72 + qd * 16];
            float v[16];
#pragma unroll
            for (int j = 0; j < 4; j++) {
                float4 x = *(float4*)(row + j * 4);
                v[j * 4 + 0] = x.x * gscale; v[j * 4 + 1] = x.y * gscale;
                v[j * 4 + 2] = x.z * gscale; v[j * 4 + 3] = x.w * gscale;
            }
            float mx = v[0];
#pragma unroll
            for (int i = 1; i < 16; i++) mx = fmaxf(mx, v[i]);
            mx = fmaxf(mx, __shfl_xor_sync(0xffffffffu, mx, 1));
            mx = fmaxf(mx, __shfl_xor_sync(0xffffffffu, mx, 2));

            const float mold = m_s[r];
            const float nm = fmaxf(mold, mx);
            float sum = 0.f;
#pragma unroll
            for (int i = 0; i < 16; i++) { v[i] = __expf(v[i] - nm); sum += v[i]; }
#pragma unroll
            for (int j = 0; j < 4; j++)
                *(float4*)(row + j * 4) =
                    make_float4(v[j * 4 + 0], v[j * 4 + 1], v[j * 4 + 2], v[j * 4 + 3]);
            sum += __shfl_xor_sync(0xffffffffu, sum, 1);
            sum += __shfl_xor_sync(0xffffffffu, sum, 2);
            if (qd == 0) {
                float corr = __expf(mold - nm);
                l_s[r] = l_s[r] * corr + sum;
                m_s[r] = nm;
                corr_s[r] = corr;
            }
        }
        __syncthreads();

        // ---- rescale O accumulators by per-row corr (row-index fragment)
#pragma unroll
        for (int j = 0; j < 2; j++)
#pragma unroll
            for (int e = 0; e < 8; e++)
                of[j].x[e] *= corr_s[16 * wr + (int)rowidx.x[e]];

        // ---- O += P V   (P in Ss row-major, V in Vs row-major)
#pragma unroll
        for (int k = 0; k < 8; k++) {
            FragA pf;
            wmma::load_matrix_sync(pf, &Ss[(16 * wr) * 72 + 8 * k], 72);
            to_tf32(pf);
#pragma unroll
            for (int j = 0; j < 2; j++) {
                FragBr vf;
                wmma::load_matrix_sync(vf, &Vs[(8 * k) * 72 + 32 * wc + 16 * j], 72);
                to_tf32(vf);
                wmma::mma_sync(of[j], pf, vf, of[j]);
            }
        }
        __syncthreads();   // protect Ks/Vs/Ss before next tile
    }

    // epilogue: normalize rows, store
    if (tid < 64) corr_s[tid] = 1.0f / l_s[tid];
    __syncthreads();
#pragma unroll
    for (int j = 0; j < 2; j++) {
#pragma unroll
        for (int e = 0; e < 8; e++)
            of[j].x[e] *= corr_s[16 * wr + (int)rowidx.x[e]];
        wmma::store_matrix_sync(
            O + (size_t)(b * T + q0 + 16 * wr) * D + h * DH + 32 * wc + 16 * j,
            of[j], D, wmma::mem_row_major);
    }
}

// ----------------------------- launch ---------------------------------------
extern "C" void kernel_launch(void* const* d_in, const int* in_sizes, int n_in,
                              void* d_out, int out_size)
{
    using namespace cfg;
    (void)in_sizes; (void)n_in; (void)out_size;

    const float* query  = (const float*)d_in[0];
    const float* key    = (const float*)d_in[1];
    const float* value  = (const float*)d_in[2];
    const float* memory = (const float*)d_in[3];
    const float* Wq = (const float*)d_in[4];
    const float* bq = (const float*)d_in[5];
    const float* Wk = (const float*)d_in[6];
    const float* bk = (const float*)d_in[7];
    const float* Wv = (const float*)d_in[8];
    const float* bv = (const float*)d_in[9];
    const float* Wo = (const float*)d_in[10];
    const float* bo = (const float*)d_in[11];
    const float* Wg = (const float*)d_in[12];
    const float* bg = (const float*)d_in[13];
    float* out = (float*)d_out;

    void *pQ, *pK, *pV, *pO;
    cudaGetSymbolAddress(&pQ, g_Q);
    cudaGetSymbolAddress(&pK, g_K);
    cudaGetSymbolAddress(&pV, g_V);
    cudaGetSymbolAddress(&pO, g_O);

    cudaFuncSetAttribute(flash_tf32_kernel,
                         cudaFuncAttributeMaxDynamicSharedMemorySize, FL_SMEM);

    // gate path
    mean_kernel<<<dim3(D / 256, B), 256>>>(query, memory);
    gate_vals_kernel<<<dim3(D / 256, B), 256>>>(Wg, bg);
    gate_reduce_kernel<<<1, 1024>>>();

    // projections (tf32 tensor cores)
    dim3 gg(D / 128, BT / 128);
    gemm_tf32_kernel<<<gg, 256>>>(query, Wq, bq, (float*)pQ, BT, D, D);
    gemm_tf32_kernel<<<gg, 256>>>(key,   Wk, bk, (float*)pK, BT, D, D);
    gemm_tf32_kernel<<<gg, 256>>>(value, Wv, bv, (float*)pV, BT, D, D);

    // attention (tf32 tensor cores)
    flash_tf32_kernel<<<dim3(T / 64, H, B), 256, FL_SMEM>>>(
        (const float*)pQ, (const float*)pK, (const float*)pV, (float*)pO);

    // output projection -> d_out
    gemm_tf32_kernel<<<gg, 256>>>((const float*)pO, Wo, bo, out, BT, D, D);
}

// round 4
// speedup vs baseline: 1.3962x; 1.0599x over previous
#include <cuda_runtime.h>
#include <mma.h>
#include <math.h>

using namespace nvcuda;

// ---------------------------------------------------------------------------
// MemoryGatedAttention  (B=4, T=S=2048, D=1024, H=16, DH=64, M=64)
// Round 4 (re-bench of R3 after infra failure):
//   tf32 wmma + cp.async double buffering; 128-row flash tile.
// ---------------------------------------------------------------------------

namespace cfg {
constexpr int B  = 4;
constexpr int T  = 2048;
constexpr int S  = 2048;
constexpr int D  = 1024;
constexpr int H  = 16;
constexpr int DH = 64;
constexpr int M  = 64;
constexpr int BT = B * T;
constexpr int FL_LD = 68;          // smem row stride (floats)
// flash smem floats: Ks[2][64][68] + Vs[2][64][68] + Ss[128][68] + stats + idx
constexpr int FL_KS = 2 * 64 * FL_LD;              // 8704
constexpr int FL_VS = 2 * 64 * FL_LD;              // 8704
constexpr int FL_SS = 128 * FL_LD;                 // 8704
constexpr int FL_SMEM_FLOATS = FL_KS + FL_VS + FL_SS + 3 * 128 + 256;
constexpr int FL_SMEM = FL_SMEM_FLOATS * (int)sizeof(float);   // ~107KB
}

// ----------------------------- scratch --------------------------------------
__device__ float g_Q[cfg::B * cfg::T * cfg::D];
__device__ float g_K[cfg::B * cfg::S * cfg::D];
__device__ float g_V[cfg::B * cfg::S * cfg::D];
__device__ float g_O[cfg::B * cfg::T * cfg::D];
__device__ float g_memin[cfg::B * 2 * cfg::D];
__device__ float g_gatevals[cfg::B * cfg::D];
__device__ float g_scale_val;

// ----------------------------- cp.async helpers ------------------------------
__device__ __forceinline__ void cp_async16(void* smem_dst, const void* gmem_src) {
    unsigned sa = (unsigned)__cvta_generic_to_shared(smem_dst);
    asm volatile("cp.async.cg.shared.global [%0], [%1], 16;\n" :: "r"(sa), "l"(gmem_src));
}
__device__ __forceinline__ void cp_commit() {
    asm volatile("cp.async.commit_group;\n");
}
template <int N>
__device__ __forceinline__ void cp_wait() {
    asm volatile("cp.async.wait_group %0;\n" :: "n"(N));
}

// ----------------------------- fragment types --------------------------------
using FragA  = wmma::fragment<wmma::matrix_a, 16, 16, 8, wmma::precision::tf32, wmma::row_major>;
using FragBr = wmma::fragment<wmma::matrix_b, 16, 16, 8, wmma::precision::tf32, wmma::row_major>;
using FragBc = wmma::fragment<wmma::matrix_b, 16, 16, 8, wmma::precision::tf32, wmma::col_major>;
using FragC  = wmma::fragment<wmma::accumulator, 16, 16, 8, float>;

template <typename F>
__device__ __forceinline__ void to_tf32(F& f) {
#pragma unroll
    for (int e = 0; e < f.num_elements; e++) f.x[e] = wmma::__float_to_tf32(f.x[e]);
}

// ----------------------------- means ----------------------------------------
__global__ void __launch_bounds__(256)
mean_kernel(const float* __restrict__ query, const float* __restrict__ memory)
{
    using namespace cfg;
    const int b = blockIdx.y;
    const int d = blockIdx.x * blockDim.x + threadIdx.x;

    const float* qp = query + (size_t)b * T * D + d;
    float s0 = 0.f, s1 = 0.f, s2 = 0.f, s3 = 0.f;
    for (int t = 0; t < T; t += 4) {
        s0 += qp[(size_t)(t + 0) * D];
        s1 += qp[(size_t)(t + 1) * D];
        s2 += qp[(size_t)(t + 2) * D];
        s3 += qp[(size_t)(t + 3) * D];
    }
    g_memin[b * 2 * D + d] = ((s0 + s1) + (s2 + s3)) * (1.0f / T);

    const float* mp = memory + (size_t)b * M * D + d;
    float u0 = 0.f, u1 = 0.f;
    for (int m = 0; m < M; m += 2) {
        u0 += mp[(size_t)(m + 0) * D];
        u1 += mp[(size_t)(m + 1) * D];
    }
    g_memin[b * 2 * D + D + d] = (u0 + u1) * (1.0f / M);
}

// ----------------------------- gate ------------------------------------------
__global__ void __launch_bounds__(256)
gate_vals_kernel(const float* __restrict__ Wg, const float* __restrict__ bg)
{
    using namespace cfg;
    const int b = blockIdx.y;
    const int j = blockIdx.x * blockDim.x + threadIdx.x;
    const float* mi = g_memin + b * 2 * D;

    float a0 = 0.f, a1 = 0.f, a2 = 0.f, a3 = 0.f;
    for (int i = 0; i < 2 * D; i += 4) {
        a0 += mi[i + 0] * Wg[(size_t)(i + 0) * D + j];
        a1 += mi[i + 1] * Wg[(size_t)(i + 1) * D + j];
        a2 += mi[i + 2] * Wg[(size_t)(i + 2) * D + j];
        a3 += mi[i + 3] * Wg[(size_t)(i + 3) * D + j];
    }
    float acc = bg[j] + ((a0 + a1) + (a2 + a3));
    g_gatevals[b * D + j] = 1.0f / (1.0f + expf(-acc));
}

__global__ void gate_reduce_kernel()
{
    using namespace cfg;
    __shared__ float red[1024];
    const int t = threadIdx.x;
    red[t] = g_gatevals[t] + g_gatevals[t + 1024] +
             g_gatevals[t + 2048] + g_gatevals[t + 3072];
    __syncthreads();
    for (int s = 512; s > 0; s >>= 1) {
        if (t < s) red[t] += red[t + s];
        __syncthreads();
    }
    if (t == 0) g_scale_val = red[0] * (1.0f / (B * D)) * 0.125f;
}

// ----------------------------- tf32 GEMM body (double-buffered) --------------
// C = A[8192,1024] @ W[1024,1024] + bias.  128x128x16 tile, 8 warps (2x4).
__device__ __forceinline__ void gemm_body(
    const float* __restrict__ A, const float* __restrict__ W,
    const float* __restrict__ bias, float* __restrict__ C)
{
    using namespace cfg;
    __shared__ float As[2][128][20];
    __shared__ float Bs[2][16][132];
    __shared__ float idxm[256];

    const int tid = threadIdx.x;
    const int warpId = tid >> 5;
    const int wr = warpId >> 2;
    const int wc = warpId & 3;
    const int m0 = blockIdx.y * 128;
    const int n0 = blockIdx.x * 128;

    idxm[tid] = (float)(tid & 15);

    const int aRow = tid >> 2, aC = (tid & 3) * 4;
    const int bRow = tid >> 5, bC = (tid & 31) * 4;

    auto issue_tile = [&](int k0, int buf) {
#pragma unroll
        for (int t = 0; t < 2; t++) {
            int r = aRow + t * 64;
            cp_async16(&As[buf][r][aC], A + (size_t)(m0 + r) * D + k0 + aC);
        }
#pragma unroll
        for (int t = 0; t < 2; t++) {
            int r = bRow + t * 8;
            cp_async16(&Bs[buf][r][bC], W + (size_t)(k0 + r) * D + n0 + bC);
        }
        cp_commit();
    };

    FragC acc[4][2];
#pragma unroll
    for (int i = 0; i < 4; i++)
#pragma unroll
        for (int j = 0; j < 2; j++) wmma::fill_fragment(acc[i][j], 0.f);

    issue_tile(0, 0);
    __syncthreads();                 // idxm visible
    FragC colidx;
    wmma::load_matrix_sync(colidx, idxm, 16, wmma::mem_row_major);

    constexpr int NIT = cfg::D / 16;     // 64
    for (int kt = 0; kt < NIT; kt++) {
        const int buf = kt & 1;
        if (kt + 1 < NIT) issue_tile((kt + 1) * 16, buf ^ 1);
        if (kt + 1 < NIT) cp_wait<1>(); else cp_wait<0>();
        __syncthreads();

#pragma unroll
        for (int kk = 0; kk < 2; kk++) {
            FragA af[4];
#pragma unroll
            for (int i = 0; i < 4; i++) {
                wmma::load_matrix_sync(af[i], &As[buf][64 * wr + 16 * i][8 * kk], 20);
                to_tf32(af[i]);
            }
            FragBr bf[2];
#pragma unroll
            for (int j = 0; j < 2; j++) {
                wmma::load_matrix_sync(bf[j], &Bs[buf][8 * kk][32 * wc + 16 * j], 132);
                to_tf32(bf[j]);
            }
#pragma unroll
            for (int i = 0; i < 4; i++)
#pragma unroll
                for (int j = 0; j < 2; j++)
                    wmma::mma_sync(acc[i][j], af[i], bf[j], acc[i][j]);
        }
        __syncthreads();             // readers done before buf is overwritten
    }

#pragma unroll
    for (int i = 0; i < 4; i++)
#pragma unroll
        for (int j = 0; j < 2; j++) {
            const int nbase = n0 + 32 * wc + 16 * j;
#pragma unroll
            for (int e = 0; e < 8; e++)
                acc[i][j].x[e] += __ldg(&bias[nbase + (int)colidx.x[e]]);
            wmma::store_matrix_sync(
                C + (size_t)(m0 + 64 * wr + 16 * i) * D + nbase,
                acc[i][j], D, wmma::mem_row_major);
        }
}

// fused QKV projection: blockIdx.z selects input/weight/output
__global__ void __launch_bounds__(256)
gemm_qkv_kernel(const float* __restrict__ q, const float* __restrict__ k,
                const float* __restrict__ v,
                const float* __restrict__ Wq, const float* __restrict__ Wk,
                const float* __restrict__ Wv,
                const float* __restrict__ bq, const float* __restrict__ bk,
                const float* __restrict__ bv,
                float* __restrict__ oq, float* __restrict__ ok,
                float* __restrict__ ov)
{
    const float *A, *W, *bias; float* C;
    if (blockIdx.z == 0)      { A = q; W = Wq; bias = bq; C = oq; }
    else if (blockIdx.z == 1) { A = k; W = Wk; bias = bk; C = ok; }
    else                      { A = v; W = Wv; bias = bv; C = ov; }
    gemm_body(A, W, bias, C);
}

__global__ void __launch_bounds__(256)
gemm_single_kernel(const float* __restrict__ A, const float* __restrict__ W,
                   const float* __restrict__ bias, float* __restrict__ C)
{
    gemm_body(A, W, bias, C);
}

// ----------------------------- tf32 flash attention --------------------------
// grid (T/128, H, B), 256 threads = 8 warps; warp w owns rows 16w..16w+15.
// K/V tiles 64 keys, double-buffered via cp.async.
__global__ void __launch_bounds__(256)
flash_tf32_kernel(const float* __restrict__ Q, const float* __restrict__ K,
                  const float* __restrict__ V, float* __restrict__ O)
{
    using namespace cfg;
    extern __shared__ float sm[];
    float* Ks     = sm;                               // [2][64][FL_LD]
    float* Vs     = sm + FL_KS;                       // [2][64][FL_LD]
    float* Ss     = sm + FL_KS + FL_VS;               // [128][FL_LD]
    float* m_s    = Ss + FL_SS;                       // [128]
    float* l_s    = m_s + 128;
    float* corr_s = l_s + 128;
    float* idxm   = corr_s + 128;                     // [256]

    const int b = blockIdx.z, h = blockIdx.y, q0 = blockIdx.x * 128;
    const int tid = threadIdx.x;
    const int w = tid >> 5;                           // warp -> rows 16w
    const float gscale = g_scale_val;

    const float* Kp = K + (size_t)b * S * D + h * DH;
    const float* Vp = V + (size_t)b * S * D + h * DH;

    idxm[tid] = (float)(tid >> 4);
    if (tid < 128) { m_s[tid] = -INFINITY; l_s[tid] = 0.f; }

    // stage Q tile (128 x 64) into Ss: 2 threads/row, 32 floats each
    {
        const int r = tid >> 1, half = tid & 1;
        const float* src = Q + (size_t)(b * T + q0 + r) * D + h * DH + half * 32;
        float* dst = &Ss[r * FL_LD + half * 32];
#pragma unroll
        for (int jj = 0; jj < 8; jj++)
            *(float4*)(dst + jj * 4) = *(const float4*)(src + jj * 4);
    }
    __syncthreads();

    FragC rowidx;
    wmma::load_matrix_sync(rowidx, idxm, 16, wmma::mem_row_major);

    FragA qf[8];
#pragma unroll
    for (int k = 0; k < 8; k++) {
        wmma::load_matrix_sync(qf[k], &Ss[(16 * w) * FL_LD + 8 * k], FL_LD);
        to_tf32(qf[k]);
    }
    FragC of[4];
#pragma unroll
    for (int j = 0; j < 4; j++) wmma::fill_fragment(of[j], 0.f);
    __syncthreads();                 // Q staging reads finished before Ss reuse

    // K/V tile loader: 64 rows x 64 floats each => 4 chunks/thread/array
    auto issue_kv = [&](int s0, int buf) {
        float* kb = Ks + buf * 64 * FL_LD;
        float* vb = Vs + buf * 64 * FL_LD;
#pragma unroll
        for (int t = 0; t < 4; t++) {
            int c = tid + t * 256;                   // 0..1023
            int row = c >> 4, col = (c & 15) * 4;
            cp_async16(&kb[row * FL_LD + col], Kp + (size_t)(s0 + row) * D + col);
        }
#pragma unroll
        for (int t = 0; t < 4; t++) {
            int c = tid + t * 256;
            int row = c >> 4, col = (c & 15) * 4;
            cp_async16(&vb[row * FL_LD + col], Vp + (size_t)(s0 + row) * D + col);
        }
        cp_commit();
    };

    issue_kv(0, 0);

    constexpr int NT = cfg::S / 64;                  // 32
    for (int it = 0; it < NT; it++) {
        const int buf = it & 1;
        if (it + 1 < NT) issue_kv((it + 1) * 64, buf ^ 1);
        if (it + 1 < NT) cp_wait<1>(); else cp_wait<0>();
        __syncthreads();

        // ---- S = Q K^T
        const float* kb = Ks + buf * 64 * FL_LD;
        FragC sf[4];
#pragma unroll
        for (int j = 0; j < 4; j++) wmma::fill_fragment(sf[j], 0.f);
#pragma unroll
        for (int k = 0; k < 8; k++) {
#pragma unroll
            for (int j = 0; j < 4; j++) {
                FragBc bf;
                wmma::load_matrix_sync(bf, &kb[(16 * j) * FL_LD + 8 * k], FL_LD);
                to_tf32(bf);
                wmma::mma_sync(sf[j], qf[k], bf, sf[j]);
            }
        }
#pragma unroll
        for (int j = 0; j < 4; j++)
            wmma::store_matrix_sync(&Ss[(16 * w) * FL_LD + 16 * j], sf[j],
                                    FL_LD, wmma::mem_row_major);
        __syncthreads();

        // ---- online softmax: 2 threads per row, 32 cols each
        {
            const int r = tid >> 1, half = tid & 1;
            float* row = &Ss[r * FL_LD + half * 32];
            float v[32];
#pragma unroll
            for (int jj = 0; jj < 8; jj++) {
                float4 x = *(float4*)(row + jj * 4);
                v[jj * 4 + 0] = x.x * gscale; v[jj * 4 + 1] = x.y * gscale;
                v[jj * 4 + 2] = x.z * gscale; v[jj * 4 + 3] = x.w * gscale;
            }
            float mx = v[0];
#pragma unroll
            for (int i = 1; i < 32; i++) mx = fmaxf(mx, v[i]);
            mx = fmaxf(mx, __shfl_xor_sync(0xffffffffu, mx, 1));

            const float mold = m_s[r];
            const float nm = fmaxf(mold, mx);
            float sum = 0.f;
#pragma unroll
            for (int i = 0; i < 32; i++) { v[i] = __expf(v[i] - nm); sum += v[i]; }
#pragma unroll
            for (int jj = 0; jj < 8; jj++)
                *(float4*)(row + jj * 4) =
                    make_float4(v[jj * 4 + 0], v[jj * 4 + 1],
                                v[jj * 4 + 2], v[jj * 4 + 3]);
            sum += __shfl_xor_sync(0xffffffffu, sum, 1);
            if (half == 0) {
                float corr = __expf(mold - nm);
                l_s[r] = l_s[r] * corr + sum;
                m_s[r] = nm;
                corr_s[r] = corr;
            }
        }
        __syncthreads();

        // ---- rescale O accumulators
#pragma unroll
        for (int j = 0; j < 4; j++)
#pragma unroll
            for (int e = 0; e < 8; e++)
                of[j].x[e] *= corr_s[16 * w + (int)rowidx.x[e]];

        // ---- O += P V
        const float* vb = Vs + buf * 64 * FL_LD;
#pragma unroll
        for (int k = 0; k < 8; k++) {
            FragA pf;
            wmma::load_matrix_sync(pf, &Ss[(16 * w) * FL_LD + 8 * k], FL_LD);
            to_tf32(pf);
#pragma unroll
            for (int j = 0; j < 4; j++) {
                FragBr vf;
                wmma::load_matrix_sync(vf, &vb[(8 * k) * FL_LD + 16 * j], FL_LD);
                to_tf32(vf);
                wmma::mma_sync(of[j], pf, vf, of[j]);
            }
        }
        __syncthreads();   // Ss / Vs[buf] free before next tile's writes
    }

    // epilogue
    if (tid < 128) corr_s[tid] = 1.0f / l_s[tid];
    __syncthreads();
#pragma unroll
    for (int j = 0; j < 4; j++) {
#pragma unroll
        for (int e = 0; e < 8; e++)
            of[j].x[e] *= corr_s[16 * w + (int)rowidx.x[e]];
        wmma::store_matrix_sync(
            O + (size_t)(b * T + q0 + 16 * w) * D + h * DH + 16 * j,
            of[j], D, wmma::mem_row_major);
    }
}

// ----------------------------- launch ----------------------------------------
extern "C" void kernel_launch(void* const* d_in, const int* in_sizes, int n_in,
                              void* d_out, int out_size)
{
    using namespace cfg;
    (void)in_sizes; (void)n_in; (void)out_size;

    const float* query  = (const float*)d_in[0];
    const float* key    = (const float*)d_in[1];
    const float* value  = (const float*)d_in[2];
    const float* memory = (const float*)d_in[3];
    const float* Wq = (const float*)d_in[4];
    const float* bq = (const float*)d_in[5];
    const float* Wk = (const float*)d_in[6];
    const float* bk = (const float*)d_in[7];
    const float* Wv = (const float*)d_in[8];
    const float* bv = (const float*)d_in[9];
    const float* Wo = (const float*)d_in[10];
    const float* bo = (const float*)d_in[11];
    const float* Wg = (const float*)d_in[12];
    const float* bg = (const float*)d_in[13];
    float* out = (float*)d_out;

    void *pQ, *pK, *pV, *pO;
    cudaGetSymbolAddress(&pQ, g_Q);
    cudaGetSymbolAddress(&pK, g_K);
    cudaGetSymbolAddress(&pV, g_V);
    cudaGetSymbolAddress(&pO, g_O);

    cudaFuncSetAttribute(flash_tf32_kernel,
                         cudaFuncAttributeMaxDynamicSharedMemorySize, FL_SMEM);

    // gate path
    mean_kernel<<<dim3(D / 256, B), 256>>>(query, memory);
    gate_vals_kernel<<<dim3(D / 256, B), 256>>>(Wg, bg);
    gate_reduce_kernel<<<1, 1024>>>();

    // fused QKV projections
    gemm_qkv_kernel<<<dim3(D / 128, BT / 128, 3), 256>>>(
        query, key, value, Wq, Wk, Wv, bq, bk, bv,
        (float*)pQ, (float*)pK, (float*)pV);

    // attention
    flash_tf32_kernel<<<dim3(T / 128, H, B), 256, FL_SMEM>>>(
        (const float*)pQ, (const float*)pK, (const float*)pV, (float*)pO);

    // output projection -> d_out
    gemm_single_kernel<<<dim3(D / 128, BT / 128), 256>>>(
        (const float*)pO, Wo, bo, out);
}